// round 2
// baseline (speedup 1.0000x reference)
#include <cuda_runtime.h>
#include <cuda_bf16.h>
#include <math.h>

#define N 6400
#define L 21
#define HW 80
#define NS 16          // split-K chunks
#define CHUNK (N / NS) // 400
#define JT 100         // smem staging subtile
#define NPAIR 11       // ceil(22/2) label pairs (l=21 is a zero dummy)

// ---------------- device globals (scratch; allocation-free rule) -------------
static __device__ float g_K[(size_t)N * N];      // 163.84 MB bilateral kernel
static __device__ float g_normbi[N];
static __device__ float g_normsp[N];
static __device__ float4 g_featA[N];             // x/160, y/160, r/3, g/3
static __device__ float  g_featB[N];             // b/3
static __device__ float  g_sqf[N];               // ||f_i||^2 (5-dim)
static __device__ float  g_g1dT[HW * HW];        // g1dT[xp*80 + x] = exp(-(x-xp)^2/18)
static __device__ float  g_Msp[L * L];           // C @ Wsp
static __device__ float  g_Mbi[L * L];           // C @ Wbi
static __device__ float  g_q[L * N];
static __device__ float  g_tmp[L * N];
static __device__ float  g_sp[L * N];            // spatial filtered (pre-norm)
static __device__ float  g_cur[L * N];
static __device__ float  g_part[NS][L * N];      // bilateral split-K partials

// ---------------- f32x2 helpers ---------------------------------------------
__device__ __forceinline__ unsigned long long pack2(float v) {
    unsigned long long r;
    asm("mov.b64 %0, {%1, %2};" : "=l"(r) : "f"(v), "f"(v));
    return r;
}
__device__ __forceinline__ void ffma2(unsigned long long& acc,
                                      unsigned long long a,
                                      unsigned long long b) {
    asm("fma.rn.f32x2 %0, %1, %2, %0;" : "+l"(acc) : "l"(a), "l"(b));
}
__device__ __forceinline__ void unpack2(unsigned long long v, float& lo, float& hi) {
    asm("mov.b64 {%0, %1}, %2;" : "=f"(lo), "=f"(hi) : "l"(v));
}

// ---------------- precompute kernels -----------------------------------------
__global__ void k_tables(const float* __restrict__ image) {
    int idx = blockIdx.x * 256 + threadIdx.x;
    if (idx >= N) return;
    // 1D spatial gaussian table: idx = xp*80 + x
    {
        int xp = idx / HW, xx = idx % HW;
        float d = (float)(xx - xp);
        g_g1dT[idx] = expf(-d * d / 18.0f);
    }
    // per-pixel bilateral features + spatial norm
    int x = idx % HW, y = idx / HW;
    float r = image[idx];
    float g = image[N + idx];
    float b = image[2 * N + idx];
    float4 fA;
    fA.x = (float)x / 160.0f;
    fA.y = (float)y / 160.0f;
    fA.z = r / 3.0f;
    fA.w = g / 3.0f;
    float fB = b / 3.0f;
    g_featA[idx] = fA;
    g_featB[idx] = fB;
    g_sqf[idx] = fA.x * fA.x + fA.y * fA.y + fA.z * fA.z + fA.w * fA.w + fB * fB;
    float Sx = 0.0f, Sy = 0.0f;
    for (int t = 0; t < HW; t++) {
        float dx = (float)(x - t);
        float dy = (float)(y - t);
        Sx += expf(-dx * dx / 18.0f);
        Sy += expf(-dy * dy / 18.0f);
    }
    g_normsp[idx] = 1.0f / (Sx * Sy + 1e-8f);
}

__global__ void k_mats(const float* __restrict__ Wsp,
                       const float* __restrict__ Wbi,
                       const float* __restrict__ C) {
    int t = threadIdx.x;
    if (t >= L * L) return;
    int l = t / L, m = t % L;
    float a = 0.0f, b = 0.0f;
    for (int k = 0; k < L; k++) {
        a += C[l * L + k] * Wsp[k * L + m];
        b += C[l * L + k] * Wbi[k * L + m];
    }
    g_Msp[t] = a;
    g_Mbi[t] = b;
}

// one block per row i: compute K_bi[i][:] + row sum
__global__ void k_kbi() {
    __shared__ float red[256];
    int i = blockIdx.x;
    float4 fa = g_featA[i];
    float fb = g_featB[i];
    float sqi = g_sqf[i];
    float sum = 0.0f;
    for (int j = threadIdx.x; j < N; j += 256) {
        float4 ga = g_featA[j];
        float gb = g_featB[j];
        float dot = fa.x * ga.x + fa.y * ga.y + fa.z * ga.z + fa.w * ga.w + fb * gb;
        float d2 = sqi + g_sqf[j] - 2.0f * dot;
        d2 = fmaxf(d2, 0.0f);
        float kv = __expf(-0.5f * d2);
        g_K[(size_t)i * N + j] = kv;
        sum += kv;
    }
    red[threadIdx.x] = sum;
    __syncthreads();
    for (int s = 128; s > 0; s >>= 1) {
        if (threadIdx.x < s) red[threadIdx.x] += red[threadIdx.x + s];
        __syncthreads();
    }
    if (threadIdx.x == 0) g_normbi[i] = 1.0f / (red[0] + 1e-8f);
}

// ---------------- per-iteration kernels --------------------------------------
__global__ void k_softmax(const float* __restrict__ logits, int first) {
    int i = blockIdx.x * 256 + threadIdx.x;
    if (i >= N) return;
    const float* src = first ? logits : g_cur;
    float v[L];
    float m = -1e30f;
    #pragma unroll
    for (int l = 0; l < L; l++) {
        v[l] = src[l * N + i];
        m = fmaxf(m, v[l]);
    }
    float s = 0.0f;
    #pragma unroll
    for (int l = 0; l < L; l++) {
        v[l] = __expf(v[l] - m);
        s += v[l];
    }
    float rinv = 1.0f / s;
    #pragma unroll
    for (int l = 0; l < L; l++) g_q[l * N + i] = v[l] * rinv;
}

// dense 80-tap blur along x: tmp[l,y,x] = sum_xp g(x,xp) q[l,y,xp]
__global__ void k_blurx() {
    __shared__ float s[4][HW];
    int l = blockIdx.x;
    int y = blockIdx.y * 4 + threadIdx.y;
    int x = threadIdx.x;
    s[threadIdx.y][x] = g_q[l * N + y * HW + x];
    __syncthreads();
    float acc = 0.0f;
    #pragma unroll 16
    for (int xp = 0; xp < HW; xp++)
        acc += g_g1dT[xp * HW + x] * s[threadIdx.y][xp];
    g_tmp[l * N + y * HW + x] = acc;
}

// dense 80-tap blur along y: sp[l,y,x] = sum_yp g(y,yp) tmp[l,yp,x]
__global__ void k_blury() {
    __shared__ float s[N / 1 > 6400 ? 1 : 6400];  // 6400 floats = 25.6 KB
    int l = blockIdx.x;
    int lin = threadIdx.y * HW + threadIdx.x;     // 640 threads
    for (int r = lin; r < 6400; r += 640) s[r] = g_tmp[l * N + r];
    __syncthreads();
    int x = threadIdx.x;
    int y = blockIdx.y * 8 + threadIdx.y;
    float acc = 0.0f;
    #pragma unroll 16
    for (int yp = 0; yp < HW; yp++)
        acc += g_g1dT[yp * HW + y] * s[yp * HW + x];
    g_sp[l * N + y * HW + x] = acc;
}

// bilateral split-K GEMM: part[c][l][i] = sum_{j in chunk c} K[j][i] * q[l][j]
__global__ void k_gemm() {
    __shared__ float sq[JT * 24];
    int i = blockIdx.x * 256 + threadIdx.x;
    int j0 = blockIdx.y * CHUNK;
    unsigned long long acc[NPAIR];
    #pragma unroll
    for (int p = 0; p < NPAIR; p++) acc[p] = 0ULL;

    for (int st = 0; st < CHUNK / JT; st++) {
        int jb = j0 + st * JT;
        __syncthreads();
        for (int idx = threadIdx.x; idx < JT * 24; idx += 256) {
            int l = idx / JT, j = idx % JT;        // coalesced over j
            float v = (l < L) ? g_q[l * N + jb + j] : 0.0f;
            sq[j * 24 + l] = v;
        }
        __syncthreads();
        const unsigned long long* sq2 = (const unsigned long long*)sq;
        #pragma unroll 4
        for (int j = 0; j < JT; j++) {
            float kv = g_K[(size_t)(jb + j) * N + i];  // symmetric: K[j][i]=K[i][j]
            unsigned long long k2 = pack2(kv);
            const unsigned long long* row = sq2 + j * 12;
            #pragma unroll
            for (int p = 0; p < NPAIR; p++) ffma2(acc[p], k2, row[p]);
        }
    }
    #pragma unroll
    for (int p = 0; p < NPAIR; p++) {
        float lo, hi;
        unpack2(acc[p], lo, hi);
        g_part[blockIdx.y][(2 * p) * N + i] = lo;
        if (2 * p + 1 < L) g_part[blockIdx.y][(2 * p + 1) * N + i] = hi;
    }
}

// reduce partials, apply norms, mix with folded L x L matrices, add unary
__global__ void k_combine(const float* __restrict__ logits, float* __restrict__ dout,
                          int last) {
    __shared__ float msp[L * L], mbi[L * L];
    for (int idx = threadIdx.x; idx < L * L; idx += 256) {
        msp[idx] = g_Msp[idx];
        mbi[idx] = g_Mbi[idx];
    }
    __syncthreads();
    int i = blockIdx.x * 256 + threadIdx.x;
    if (i >= N) return;
    float nsp = g_normsp[i];
    float nbi = g_normbi[i];
    float acc[L];
    #pragma unroll
    for (int l = 0; l < L; l++) acc[l] = 0.0f;
    for (int m = 0; m < L; m++) {
        float s = g_sp[m * N + i] * nsp;
        float b = 0.0f;
        #pragma unroll
        for (int c = 0; c < NS; c++) b += g_part[c][m * N + i];
        b *= nbi;
        #pragma unroll
        for (int l = 0; l < L; l++)
            acc[l] += msp[l * L + m] * s + mbi[l * L + m] * b;
    }
    if (last) {
        #pragma unroll
        for (int l = 0; l < L; l++) dout[l * N + i] = logits[l * N + i] + acc[l];
    } else {
        #pragma unroll
        for (int l = 0; l < L; l++) g_cur[l * N + i] = logits[l * N + i] + acc[l];
    }
}

// ---------------- launch ------------------------------------------------------
extern "C" void kernel_launch(void* const* d_in, const int* in_sizes, int n_in,
                              void* d_out, int out_size) {
    const float* image = (const float*)d_in[0];   // [1,3,80,80]
    const float* logits = (const float*)d_in[1];  // [1,21,80,80]
    const float* Wsp = (const float*)d_in[2];     // [21,21]
    const float* Wbi = (const float*)d_in[3];     // [21,21]
    const float* C = (const float*)d_in[4];       // [21,21]
    float* out = (float*)d_out;

    k_tables<<<25, 256>>>(image);
    k_mats<<<1, L * L>>>(Wsp, Wbi, C);
    k_kbi<<<N, 256>>>();

    for (int it = 0; it < 5; it++) {
        k_softmax<<<25, 256>>>(logits, it == 0 ? 1 : 0);
        k_blurx<<<dim3(L, HW / 4), dim3(HW, 4)>>>();
        k_blury<<<dim3(L, HW / 8), dim3(HW, 8)>>>();
        k_gemm<<<dim3(25, NS), 256>>>();
        k_combine<<<25, 256>>>(logits, out, it == 4 ? 1 : 0);
    }
}

// round 4
// speedup vs baseline: 1.1414x; 1.1414x over previous
#include <cuda_runtime.h>
#include <cuda_fp16.h>
#include <math.h>

#define N 6400
#define L 21
#define HW 80
#define NS 32          // split-K chunks
#define CHUNK (N / NS) // 200
#define JT 100         // smem staging subtile
#define NPAIR 11       // ceil(22/2) label pairs (l=21 is a zero dummy)

// ---------------- device globals (scratch; allocation-free rule) -------------
static __device__ __half g_Kh[(size_t)N * N];    // 81.92 MB bilateral kernel (fp16, L2-resident)
static __device__ float g_normbi[N];
static __device__ float g_normsp[N];
static __device__ float4 g_featA[N];             // x/160, y/160, r/3, g/3
static __device__ float  g_featB[N];             // b/3
static __device__ float  g_sqf[N];               // ||f_i||^2 (5-dim)
static __device__ float  g_g1dT[HW * HW];        // g1dT[xp*80 + x] = exp(-(x-xp)^2/18)
static __device__ float  g_Msp[L * L];           // C @ Wsp
static __device__ float  g_Mbi[L * L];           // C @ Wbi
static __device__ float  g_q[L * N];
static __device__ float  g_tmp[L * N];
static __device__ float  g_sp[L * N];            // spatial filtered (pre-norm)
static __device__ float  g_part[NS][L * N];      // bilateral split-K partials

// ---------------- f32x2 helpers ---------------------------------------------
__device__ __forceinline__ unsigned long long pack2(float v) {
    unsigned long long r;
    asm("mov.b64 %0, {%1, %2};" : "=l"(r) : "f"(v), "f"(v));
    return r;
}
__device__ __forceinline__ void ffma2(unsigned long long& acc,
                                      unsigned long long a,
                                      unsigned long long b) {
    asm("fma.rn.f32x2 %0, %1, %2, %0;" : "+l"(acc) : "l"(a), "l"(b));
}
__device__ __forceinline__ void unpack2(unsigned long long v, float& lo, float& hi) {
    asm("mov.b64 {%0, %1}, %2;" : "=f"(lo), "=f"(hi) : "l"(v));
}

// ---------------- precompute kernels -----------------------------------------
__global__ void k_tables(const float* __restrict__ image) {
    int idx = blockIdx.x * 256 + threadIdx.x;
    if (idx >= N) return;
    // 1D spatial gaussian table: idx = xp*80 + x
    {
        int xp = idx / HW, xx = idx % HW;
        float d = (float)(xx - xp);
        g_g1dT[idx] = expf(-d * d / 18.0f);
    }
    // per-pixel bilateral features + spatial norm
    int x = idx % HW, y = idx / HW;
    float r = image[idx];
    float g = image[N + idx];
    float b = image[2 * N + idx];
    float4 fA;
    fA.x = (float)x / 160.0f;
    fA.y = (float)y / 160.0f;
    fA.z = r / 3.0f;
    fA.w = g / 3.0f;
    float fB = b / 3.0f;
    g_featA[idx] = fA;
    g_featB[idx] = fB;
    g_sqf[idx] = fA.x * fA.x + fA.y * fA.y + fA.z * fA.z + fA.w * fA.w + fB * fB;
    float Sx = 0.0f, Sy = 0.0f;
    for (int t = 0; t < HW; t++) {
        float dx = (float)(x - t);
        float dy = (float)(y - t);
        Sx += expf(-dx * dx / 18.0f);
        Sy += expf(-dy * dy / 18.0f);
    }
    g_normsp[idx] = 1.0f / (Sx * Sy + 1e-8f);
}

__global__ void k_mats(const float* __restrict__ Wsp,
                       const float* __restrict__ Wbi,
                       const float* __restrict__ C) {
    int t = threadIdx.x;
    if (t >= L * L) return;
    int l = t / L, m = t % L;
    float a = 0.0f, b = 0.0f;
    for (int k = 0; k < L; k++) {
        a += C[l * L + k] * Wsp[k * L + m];
        b += C[l * L + k] * Wbi[k * L + m];
    }
    g_Msp[t] = a;
    g_Mbi[t] = b;
}

// one block per row i: compute K_bi[i][:] (fp16) + fp32 row sum
__global__ void k_kbi() {
    __shared__ float red[256];
    int i = blockIdx.x;
    float4 fa = g_featA[i];
    float fb = g_featB[i];
    float sqi = g_sqf[i];
    float sum = 0.0f;
    for (int j = threadIdx.x; j < N; j += 256) {
        float4 ga = g_featA[j];
        float gb = g_featB[j];
        float dot = fa.x * ga.x + fa.y * ga.y + fa.z * ga.z + fa.w * ga.w + fb * gb;
        float d2 = sqi + g_sqf[j] - 2.0f * dot;
        d2 = fmaxf(d2, 0.0f);
        float kv = __expf(-0.5f * d2);
        g_Kh[(size_t)i * N + j] = __float2half_rn(kv);
        sum += kv;
    }
    red[threadIdx.x] = sum;
    __syncthreads();
    for (int s = 128; s > 0; s >>= 1) {
        if (threadIdx.x < s) red[threadIdx.x] += red[threadIdx.x + s];
        __syncthreads();
    }
    if (threadIdx.x == 0) g_normbi[i] = 1.0f / (red[0] + 1e-8f);
}

// ---------------- per-iteration kernels --------------------------------------
// warp-per-pixel initial softmax: 800 blocks x 256 threads = 6400 warps
__global__ void k_softmax0(const float* __restrict__ logits) {
    int i = (blockIdx.x * 256 + threadIdx.x) >> 5;
    int lane = threadIdx.x & 31;
    float v = (lane < L) ? logits[lane * N + i] : -1e30f;
    float m = v;
    #pragma unroll
    for (int off = 16; off > 0; off >>= 1)
        m = fmaxf(m, __shfl_xor_sync(0xffffffffu, m, off));
    float e = (lane < L) ? __expf(v - m) : 0.0f;
    float s = e;
    #pragma unroll
    for (int off = 16; off > 0; off >>= 1)
        s += __shfl_xor_sync(0xffffffffu, s, off);
    if (lane < L) g_q[lane * N + i] = e / s;
}

// dense 80-tap blur along x: tmp[l,y,x] = sum_xp g(x,xp) q[l,y,xp]
__global__ void k_blurx() {
    __shared__ float s[4][HW];
    int l = blockIdx.x;
    int y = blockIdx.y * 4 + threadIdx.y;
    int x = threadIdx.x;
    s[threadIdx.y][x] = g_q[l * N + y * HW + x];
    __syncthreads();
    float acc = 0.0f;
    #pragma unroll 16
    for (int xp = 0; xp < HW; xp++)
        acc += g_g1dT[xp * HW + x] * s[threadIdx.y][xp];
    g_tmp[l * N + y * HW + x] = acc;
}

// dense 80-tap blur along y: sp[l,y,x] = sum_yp g(y,yp) tmp[l,yp,x]
__global__ void k_blury() {
    __shared__ float s[N];
    int l = blockIdx.x;
    int lin = threadIdx.y * HW + threadIdx.x;     // 640 threads
    for (int r = lin; r < N; r += 640) s[r] = g_tmp[l * N + r];
    __syncthreads();
    int x = threadIdx.x;
    int y = blockIdx.y * 8 + threadIdx.y;
    float acc = 0.0f;
    #pragma unroll 16
    for (int yp = 0; yp < HW; yp++)
        acc += g_g1dT[yp * HW + y] * s[yp * HW + x];
    g_sp[l * N + y * HW + x] = acc;
}

// bilateral split-K GEMM: part[c][l][i] = sum_{j in chunk c} K[j][i] * q[l][j]
__global__ void k_gemm() {
    __shared__ float sq[JT * 24];
    int i = blockIdx.x * 256 + threadIdx.x;
    int j0 = blockIdx.y * CHUNK;
    unsigned long long acc[NPAIR];
    #pragma unroll
    for (int p = 0; p < NPAIR; p++) acc[p] = 0ULL;

    for (int st = 0; st < CHUNK / JT; st++) {
        int jb = j0 + st * JT;
        __syncthreads();
        for (int idx = threadIdx.x; idx < JT * 24; idx += 256) {
            int l = idx / JT, j = idx % JT;        // coalesced over j
            float v = (l < L) ? g_q[l * N + jb + j] : 0.0f;
            sq[j * 24 + l] = v;
        }
        __syncthreads();
        const unsigned long long* sq2 = (const unsigned long long*)sq;
        #pragma unroll 4
        for (int j = 0; j < JT; j++) {
            float kv = __half2float(g_Kh[(size_t)(jb + j) * N + i]);  // K symmetric
            unsigned long long k2 = pack2(kv);
            const unsigned long long* row = sq2 + j * 12;
            #pragma unroll
            for (int p = 0; p < NPAIR; p++) ffma2(acc[p], k2, row[p]);
        }
    }
    #pragma unroll
    for (int p = 0; p < NPAIR; p++) {
        float lo, hi;
        unpack2(acc[p], lo, hi);
        g_part[blockIdx.y][(2 * p) * N + i] = lo;
        if (2 * p + 1 < L) g_part[blockIdx.y][(2 * p + 1) * N + i] = hi;
    }
}

// warp-per-pixel: reduce partials, apply norms, mix with folded L x L mats,
// add unary, then (except last iter) compute softmax -> g_q for next iter.
__global__ void k_combine(const float* __restrict__ logits, float* __restrict__ dout,
                          int last) {
    __shared__ float msp[L * L], mbi[L * L];
    __shared__ float sv[8][L], bv[8][L];
    for (int idx = threadIdx.x; idx < L * L; idx += 256) {
        msp[idx] = g_Msp[idx];
        mbi[idx] = g_Mbi[idx];
    }
    __syncthreads();
    int wid = threadIdx.x >> 5;
    int lane = threadIdx.x & 31;
    int i = blockIdx.x * 8 + wid;

    if (lane < L) {
        float s = g_sp[lane * N + i] * g_normsp[i];
        float b = 0.0f;
        #pragma unroll
        for (int c = 0; c < NS; c++) b += g_part[c][lane * N + i];
        b *= g_normbi[i];
        sv[wid][lane] = s;
        bv[wid][lane] = b;
    }
    __syncwarp();

    float cur = -1e30f;
    if (lane < L) {
        float acc = 0.0f;
        #pragma unroll
        for (int m = 0; m < L; m++)
            acc += msp[lane * L + m] * sv[wid][m] + mbi[lane * L + m] * bv[wid][m];
        cur = logits[lane * N + i] + acc;
    }
    if (last) {
        if (lane < L) dout[lane * N + i] = cur;
        return;
    }
    // fused softmax (next iteration's q)
    float m = cur;
    #pragma unroll
    for (int off = 16; off > 0; off >>= 1)
        m = fmaxf(m, __shfl_xor_sync(0xffffffffu, m, off));
    float e = (lane < L) ? __expf(cur - m) : 0.0f;
    float s = e;
    #pragma unroll
    for (int off = 16; off > 0; off >>= 1)
        s += __shfl_xor_sync(0xffffffffu, s, off);
    if (lane < L) g_q[lane * N + i] = e / s;
}

// ---------------- launch ------------------------------------------------------
extern "C" void kernel_launch(void* const* d_in, const int* in_sizes, int n_in,
                              void* d_out, int out_size) {
    const float* image = (const float*)d_in[0];   // [1,3,80,80]
    const float* logits = (const float*)d_in[1];  // [1,21,80,80]
    const float* Wsp = (const float*)d_in[2];     // [21,21]
    const float* Wbi = (const float*)d_in[3];     // [21,21]
    const float* C = (const float*)d_in[4];       // [21,21]
    float* out = (float*)d_out;

    k_tables<<<25, 256>>>(image);
    k_mats<<<1, 512>>>(Wsp, Wbi, C);
    k_kbi<<<N, 256>>>();
    k_softmax0<<<800, 256>>>(logits);

    for (int it = 0; it < 5; it++) {
        k_blurx<<<dim3(L, HW / 4), dim3(HW, 4)>>>();
        k_blury<<<dim3(L, HW / 8), dim3(HW, 8)>>>();
        k_gemm<<<dim3(25, NS), 256>>>();
        k_combine<<<800, 256>>>(logits, out, it == 4 ? 1 : 0);
    }
}

// round 5
// speedup vs baseline: 1.8359x; 1.6085x over previous
#include <cuda_runtime.h>
#include <cuda_fp16.h>
#include <math.h>

#define N 6400
#define L 21
#define HW 80
#define NSJ 10          // split-j chunks for bilateral gemm
#define JCH 640         // j per chunk
#define JSTG 128        // j per smem stage
#define ASTR 136        // smem row stride in halves (128 + 8 pad)

// ---------------- device globals (scratch; allocation-free rule) -------------
static __device__ __align__(16) __half g_Kh[(size_t)N * N]; // 81.92 MB fp16 K (L2-resident)
static __device__ float g_normbi[N];
static __device__ float g_normsp[N];
static __device__ float4 g_featA[N];
static __device__ float  g_featB[N];
static __device__ float  g_sqf[N];
static __device__ float  g_g1dT[HW * HW];
static __device__ float  g_Msp[L * L];
static __device__ float  g_Mbi[L * L];
static __device__ float  g_q[L * N];                        // fp32 planar (blur)
static __device__ __align__(16) __half g_qh[L * N];         // fp16 planar (gemm A)
static __device__ float  g_sp[L * N];
static __device__ float  g_part[NSJ][N * 24];               // [chunk][i*24 + l]

// ---------------- mma helpers -------------------------------------------------
__device__ __forceinline__ unsigned smem_u32(const void* p) {
    return (unsigned)__cvta_generic_to_shared(p);
}
__device__ __forceinline__ void ldmx4(unsigned* r, unsigned addr) {
    asm volatile("ldmatrix.sync.aligned.m8n8.x4.shared.b16 {%0,%1,%2,%3},[%4];"
                 : "=r"(r[0]), "=r"(r[1]), "=r"(r[2]), "=r"(r[3]) : "r"(addr));
}
__device__ __forceinline__ void ldmx4t(unsigned* r, unsigned addr) {
    asm volatile("ldmatrix.sync.aligned.m8n8.x4.trans.shared.b16 {%0,%1,%2,%3},[%4];"
                 : "=r"(r[0]), "=r"(r[1]), "=r"(r[2]), "=r"(r[3]) : "r"(addr));
}
__device__ __forceinline__ void mma16816(float* c, const unsigned* a, unsigned b0, unsigned b1) {
    asm volatile("mma.sync.aligned.m16n8k16.row.col.f32.f16.f16.f32 "
                 "{%0,%1,%2,%3},{%4,%5,%6,%7},{%8,%9},{%0,%1,%2,%3};"
                 : "+f"(c[0]), "+f"(c[1]), "+f"(c[2]), "+f"(c[3])
                 : "r"(a[0]), "r"(a[1]), "r"(a[2]), "r"(a[3]), "r"(b0), "r"(b1));
}

// ---------------- setup: tables + initial softmax (fused) ---------------------
__global__ void k_init(const float* __restrict__ image, const float* __restrict__ logits) {
    int gtid = blockIdx.x * 256 + threadIdx.x;
    // warp-per-pixel softmax -> g_q (fp32) + g_qh (fp16)
    int i = gtid >> 5;
    int lane = threadIdx.x & 31;
    float v = (lane < L) ? logits[lane * N + i] : -1e30f;
    float m = v;
    #pragma unroll
    for (int off = 16; off > 0; off >>= 1)
        m = fmaxf(m, __shfl_xor_sync(0xffffffffu, m, off));
    float e = (lane < L) ? __expf(v - m) : 0.0f;
    float s = e;
    #pragma unroll
    for (int off = 16; off > 0; off >>= 1)
        s += __shfl_xor_sync(0xffffffffu, s, off);
    if (lane < L) {
        float qv = e / s;
        g_q[lane * N + i] = qv;
        g_qh[lane * N + i] = __float2half_rn(qv);
    }
    // tables + features (blocks 0..24)
    int idx = gtid;
    if (idx < N) {
        int xp = idx / HW, xx = idx % HW;
        float d = (float)(xx - xp);
        g_g1dT[idx] = expf(-d * d / 18.0f);
        int x = idx % HW, y = idx / HW;
        float r = image[idx];
        float g = image[N + idx];
        float b = image[2 * N + idx];
        float4 fA;
        fA.x = (float)x / 160.0f;
        fA.y = (float)y / 160.0f;
        fA.z = r / 3.0f;
        fA.w = g / 3.0f;
        float fB = b / 3.0f;
        g_featA[idx] = fA;
        g_featB[idx] = fB;
        g_sqf[idx] = fA.x * fA.x + fA.y * fA.y + fA.z * fA.z + fA.w * fA.w + fB * fB;
        float Sx = 0.0f, Sy = 0.0f;
        for (int t = 0; t < HW; t++) {
            float dx = (float)(x - t);
            float dy = (float)(y - t);
            Sx += expf(-dx * dx / 18.0f);
            Sy += expf(-dy * dy / 18.0f);
        }
        g_normsp[idx] = 1.0f / (Sx * Sy + 1e-8f);
    }
}

__global__ void k_mats(const float* __restrict__ Wsp,
                       const float* __restrict__ Wbi,
                       const float* __restrict__ C) {
    int t = threadIdx.x;
    if (t >= L * L) return;
    int l = t / L, m = t % L;
    float a = 0.0f, b = 0.0f;
    for (int k = 0; k < L; k++) {
        a += C[l * L + k] * Wsp[k * L + m];
        b += C[l * L + k] * Wbi[k * L + m];
    }
    g_Msp[t] = a;
    g_Mbi[t] = b;
}

// one block per row i: K_bi[i][:] (fp16) + fp32 row sum
__global__ void k_kbi() {
    __shared__ float red[256];
    int i = blockIdx.x;
    float4 fa = g_featA[i];
    float fb = g_featB[i];
    float sqi = g_sqf[i];
    float sum = 0.0f;
    for (int j = threadIdx.x; j < N; j += 256) {
        float4 ga = g_featA[j];
        float gb = g_featB[j];
        float dot = fa.x * ga.x + fa.y * ga.y + fa.z * ga.z + fa.w * ga.w + fb * gb;
        float d2 = sqi + g_sqf[j] - 2.0f * dot;
        d2 = fmaxf(d2, 0.0f);
        float kv = __expf(-0.5f * d2);
        g_Kh[(size_t)i * N + j] = __float2half_rn(kv);
        sum += kv;
    }
    red[threadIdx.x] = sum;
    __syncthreads();
    for (int s = 128; s > 0; s >>= 1) {
        if (threadIdx.x < s) red[threadIdx.x] += red[threadIdx.x + s];
        __syncthreads();
    }
    if (threadIdx.x == 0) g_normbi[i] = 1.0f / (red[0] + 1e-8f);
}

// ---------------- fused per-iteration: blur (blocks 0..20) + HMMA gemm -------
__global__ void __launch_bounds__(256) k_fused() {
    __shared__ __align__(16) unsigned char sraw[(JSTG + 32) * ASTR * 2];  // 43.5 KB
    int t = threadIdx.x;

    if (blockIdx.x < L) {
        // ---- spatial blur for label l: x-pass then y-pass, in-place smem ----
        float* s = (float*)sraw;  // 6400 floats = 25.6 KB
        int l = blockIdx.x;
        float reg[25];
        #pragma unroll
        for (int k = 0; k < 25; k++) s[t + k * 256] = g_q[l * N + t + k * 256];
        __syncthreads();
        #pragma unroll
        for (int k = 0; k < 25; k++) {
            int flat = t + k * 256;
            int y = flat / HW, x = flat % HW;
            float acc = 0.0f;
            #pragma unroll 8
            for (int xp = 0; xp < HW; xp++)
                acc += g_g1dT[xp * HW + x] * s[y * HW + xp];
            reg[k] = acc;
        }
        __syncthreads();
        #pragma unroll
        for (int k = 0; k < 25; k++) s[t + k * 256] = reg[k];
        __syncthreads();
        #pragma unroll
        for (int k = 0; k < 25; k++) {
            int flat = t + k * 256;
            int y = flat / HW, x = flat % HW;
            float acc = 0.0f;
            #pragma unroll 8
            for (int yp = 0; yp < HW; yp++)
                acc += g_g1dT[yp * HW + y] * s[yp * HW + x];
            g_sp[l * N + flat] = acc;
        }
        return;
    }

    // ---- bilateral gemm block: 128 i-columns x all 21 labels x 640 j ----
    __half* sB = (__half*)sraw;                       // [128][ASTR] K tile [j][i]
    __half* sA = (__half*)sraw + JSTG * ASTR;         // [32][ASTR]  q tile [l][j]
    int g = blockIdx.x - L;
    int ib0 = (g / NSJ) * 128;
    int chunk = g % NSJ;
    int jc0 = chunk * JCH;
    int wid = t >> 5, lane = t & 31;

    float acc[2][2][4];
    #pragma unroll
    for (int a = 0; a < 2; a++)
        #pragma unroll
        for (int b = 0; b < 2; b++)
            #pragma unroll
            for (int c = 0; c < 4; c++) acc[a][b][c] = 0.0f;

    unsigned sBu = smem_u32(sB);
    unsigned sAu = smem_u32(sA);

    for (int stg = 0; stg < JCH / JSTG; stg++) {
        int jbase = jc0 + stg * JSTG;
        __syncthreads();
        // fill B (K tile, row-major [j][i], coalesced): 2048 uint4
        uint4* dB = (uint4*)sB;
        #pragma unroll
        for (int k = 0; k < 8; k++) {
            int flat = t + k * 256;
            int row = flat >> 4, c16 = flat & 15;
            dB[row * (ASTR / 8) + c16] =
                *(const uint4*)(g_Kh + (size_t)(jbase + row) * N + ib0 + c16 * 8);
        }
        // fill A (q tile [l][j]): 512 uint4, rows >= 21 zero
        uint4* dA = (uint4*)sA;
        #pragma unroll
        for (int k = 0; k < 2; k++) {
            int flat = t + k * 256;
            int row = flat >> 4, c16 = flat & 15;
            uint4 v = make_uint4(0u, 0u, 0u, 0u);
            if (row < L) v = *(const uint4*)(g_qh + row * N + jbase + c16 * 8);
            dA[row * (ASTR / 8) + c16] = v;
        }
        __syncthreads();

        int arow = lane & 15;
        int cg8 = (lane >> 4) << 3;
        #pragma unroll
        for (int j0 = 0; j0 < JSTG; j0 += 16) {
            unsigned a0[4], a1[4], b[4];
            ldmx4(a0, sAu + ((arow) * ASTR + j0 + cg8) * 2);        // l 0..15
            ldmx4(a1, sAu + ((16 + arow) * ASTR + j0 + cg8) * 2);   // l 16..31
            ldmx4t(b, sBu + ((j0 + arow) * ASTR + wid * 16 + cg8) * 2);
            mma16816(acc[0][0], a0, b[0], b[1]);
            mma16816(acc[0][1], a0, b[2], b[3]);
            mma16816(acc[1][0], a1, b[0], b[1]);
            mma16816(acc[1][1], a1, b[2], b[3]);
        }
    }

    // store partials: D[l][i] frag mapping, layout g_part[chunk][i*24 + l]
    int qrow = lane >> 2;
    int qcol = (lane & 3) * 2;
    float* P = g_part[chunk];
    #pragma unroll
    for (int mt = 0; mt < 2; mt++) {
        #pragma unroll
        for (int nt = 0; nt < 2; nt++) {
            int l0 = mt * 16 + qrow;
            int l1 = l0 + 8;
            int i0 = ib0 + wid * 16 + nt * 8 + qcol;
            if (l0 < L) {
                P[i0 * 24 + l0] = acc[mt][nt][0];
                P[(i0 + 1) * 24 + l0] = acc[mt][nt][1];
            }
            if (l1 < L) {
                P[i0 * 24 + l1] = acc[mt][nt][2];
                P[(i0 + 1) * 24 + l1] = acc[mt][nt][3];
            }
        }
    }
}

// warp-per-pixel: reduce partials, norms, mix, add unary, fused softmax
__global__ void k_combine(const float* __restrict__ logits, float* __restrict__ dout,
                          int last) {
    __shared__ float msp[L * L], mbi[L * L];
    __shared__ float sv[8][L], bv[8][L];
    for (int idx = threadIdx.x; idx < L * L; idx += 256) {
        msp[idx] = g_Msp[idx];
        mbi[idx] = g_Mbi[idx];
    }
    __syncthreads();
    int wid = threadIdx.x >> 5;
    int lane = threadIdx.x & 31;
    int i = blockIdx.x * 8 + wid;

    if (lane < L) {
        float s = g_sp[lane * N + i] * g_normsp[i];
        float b = 0.0f;
        #pragma unroll
        for (int c = 0; c < NSJ; c++) b += g_part[c][i * 24 + lane];
        b *= g_normbi[i];
        sv[wid][lane] = s;
        bv[wid][lane] = b;
    }
    __syncwarp();

    float cur = -1e30f;
    if (lane < L) {
        float acc = 0.0f;
        #pragma unroll
        for (int m = 0; m < L; m++)
            acc += msp[lane * L + m] * sv[wid][m] + mbi[lane * L + m] * bv[wid][m];
        cur = logits[lane * N + i] + acc;
    }
    if (last) {
        if (lane < L) dout[lane * N + i] = cur;
        return;
    }
    float m = cur;
    #pragma unroll
    for (int off = 16; off > 0; off >>= 1)
        m = fmaxf(m, __shfl_xor_sync(0xffffffffu, m, off));
    float e = (lane < L) ? __expf(cur - m) : 0.0f;
    float s = e;
    #pragma unroll
    for (int off = 16; off > 0; off >>= 1)
        s += __shfl_xor_sync(0xffffffffu, s, off);
    if (lane < L) {
        float qv = e / s;
        g_q[lane * N + i] = qv;
        g_qh[lane * N + i] = __float2half_rn(qv);
    }
}

// ---------------- launch ------------------------------------------------------
extern "C" void kernel_launch(void* const* d_in, const int* in_sizes, int n_in,
                              void* d_out, int out_size) {
    const float* image = (const float*)d_in[0];
    const float* logits = (const float*)d_in[1];
    const float* Wsp = (const float*)d_in[2];
    const float* Wbi = (const float*)d_in[3];
    const float* C = (const float*)d_in[4];
    float* out = (float*)d_out;

    k_init<<<800, 256>>>(image, logits);
    k_mats<<<1, 512>>>(Wsp, Wbi, C);
    k_kbi<<<N, 256>>>();

    for (int it = 0; it < 5; it++) {
        k_fused<<<L + 50 * NSJ, 256>>>();
        k_combine<<<800, 256>>>(logits, out, it == 4 ? 1 : 0);
    }
}